// round 6
// baseline (speedup 1.0000x reference)
#include <cuda_runtime.h>
#include <cuda_bf16.h>
#include <cstdint>

#define N_NODES 200000
#define N_EDGES 6400000
#define HIDDEN  200
#define NHID    6
#define TM      128
#define THREADS 512
#define NCTA    ((N_NODES + TM - 1) / TM)   // 1563

#define NKC     13                  // k16 chunks (K=200 padded to 208)
#define NNT     25                  // n8 tiles (N=200)
#define NSTAGE  (NHID * NKC)        // 78
#define SLAB_B  (NNT * 32 * 16)     // 12800 bytes per (layer,kc) weight slab
#define ASTRIDE 432                 // bytes per activation row (216 bf16, conflict-free)

// smem offsets (bytes)
#define RING_OFF 0                  // 4 x SLAB_B = 51200
#define AHI_OFF  51200              // 128 x 432 = 55296
#define ALO_OFF  106496
#define BIAS_OFF 161792             // 6*200 f32 = 4800
#define WOUT_OFF 166592             // 200 f32
#define H0_OFF   167392             // 128 f32
#define ZP_OFF   167904             // 256 f32
#define SMEM_BYTES 168928

__device__ float g_agg[N_NODES];
__device__ __align__(16) uint4 g_wimg[NHID * NKC * NNT * 32];   // 998400 B

// ---------------- tiny kernels ----------------
__global__ void k_zero() {
    int i = blockIdx.x * blockDim.x + threadIdx.x;
    if (i < N_NODES) g_agg[i] = 0.0f;
}

__global__ void k_scatter(const float* __restrict__ x, const int* __restrict__ ei) {
    int i = blockIdx.x * blockDim.x + threadIdx.x;
    if (i < N_EDGES / 4) {
        const int4 s = reinterpret_cast<const int4*>(ei)[i];
        const int4 d = reinterpret_cast<const int4*>(ei + N_EDGES)[i];
        atomicAdd(&g_agg[d.x], x[s.x]);
        atomicAdd(&g_agg[d.y], x[s.y]);
        atomicAdd(&g_agg[d.z], x[s.z]);
        atomicAdd(&g_agg[d.w], x[s.w]);
    }
}

__device__ __forceinline__ uint32_t packsplit(float v0, float v1, uint32_t& lo) {
    __nv_bfloat16 h0 = __float2bfloat16(v0), h1 = __float2bfloat16(v1);
    float f0 = __bfloat162float(h0), f1 = __bfloat162float(h1);
    __nv_bfloat16 l0 = __float2bfloat16(v0 - f0), l1 = __float2bfloat16(v1 - f1);
    lo = ((uint32_t)__bfloat16_as_ushort(l1) << 16) | (uint32_t)__bfloat16_as_ushort(l0);
    return ((uint32_t)__bfloat16_as_ushort(h1) << 16) | (uint32_t)__bfloat16_as_ushort(h0);
}

// Pack w_hid into per-lane mma B-fragment order:
// idx = ((l*13+kc)*25+nt)*32 + lane -> uint4 {b0hi, b1hi, b0lo, b1lo}
__global__ void k_prep(const float* __restrict__ w_hid) {
    int idx = blockIdx.x * blockDim.x + threadIdx.x;
    if (idx >= NHID * NKC * NNT * 32) return;
    int lane = idx & 31;
    int u = idx >> 5;
    int nt = u % NNT; u /= NNT;
    int kc = u % NKC; int l = u / NKC;
    int t = lane & 3, g = lane >> 2;
    int n = nt * 8 + g;
    int k0 = kc * 16 + t * 2;
    float w00 = (k0     < HIDDEN) ? w_hid[((size_t)l * HIDDEN + k0    ) * HIDDEN + n] : 0.f;
    float w01 = (k0 + 1 < HIDDEN) ? w_hid[((size_t)l * HIDDEN + k0 + 1) * HIDDEN + n] : 0.f;
    float w10 = (k0 + 8 < HIDDEN) ? w_hid[((size_t)l * HIDDEN + k0 + 8) * HIDDEN + n] : 0.f;
    float w11 = (k0 + 9 < HIDDEN) ? w_hid[((size_t)l * HIDDEN + k0 + 9) * HIDDEN + n] : 0.f;
    uint4 v;
    uint32_t lo0, lo1;
    v.x = packsplit(w00, w01, lo0);
    v.y = packsplit(w10, w11, lo1);
    v.z = lo0;
    v.w = lo1;
    g_wimg[idx] = v;
}

// ---------------- asm helpers ----------------
__device__ __forceinline__ uint32_t s2u(const void* p) {
    uint32_t a;
    asm("{ .reg .u64 t; cvta.to.shared.u64 t, %1; cvt.u32.u64 %0, t; }" : "=r"(a) : "l"(p));
    return a;
}
__device__ __forceinline__ void cp16(uint32_t sdst, const void* gsrc) {
    asm volatile("cp.async.cg.shared.global [%0], [%1], 16;" :: "r"(sdst), "l"(gsrc));
}
#define CP_COMMIT() asm volatile("cp.async.commit_group;")
#define CP_WAIT2()  asm volatile("cp.async.wait_group 2;")

__device__ __forceinline__ void ldsm4(uint32_t* r, uint32_t a) {
    asm volatile("ldmatrix.sync.aligned.m8n8.x4.shared.b16 {%0,%1,%2,%3}, [%4];"
        : "=r"(r[0]), "=r"(r[1]), "=r"(r[2]), "=r"(r[3]) : "r"(a));
}
__device__ __forceinline__ uint4 lds128(uint32_t a) {
    uint4 v;
    asm volatile("ld.shared.v4.u32 {%0,%1,%2,%3}, [%4];"
        : "=r"(v.x), "=r"(v.y), "=r"(v.z), "=r"(v.w) : "r"(a));
    return v;
}
__device__ __forceinline__ void sts32(uint32_t a, uint32_t v) {
    asm volatile("st.shared.u32 [%0], %1;" :: "r"(a), "r"(v));
}
__device__ __forceinline__ void mma16816(float* d, const uint32_t* a, uint32_t b0, uint32_t b1) {
    asm volatile("mma.sync.aligned.m16n8k16.row.col.f32.bf16.bf16.f32 "
        "{%0,%1,%2,%3}, {%4,%5,%6,%7}, {%8,%9}, {%0,%1,%2,%3};"
        : "+f"(d[0]), "+f"(d[1]), "+f"(d[2]), "+f"(d[3])
        : "r"(a[0]), "r"(a[1]), "r"(a[2]), "r"(a[3]), "r"(b0), "r"(b1));
}

// ---------------- templated layer MMA loop (NTB = n-tile base, NNTW = tiles this warp) ----
template<int NTB, int NNTW>
__device__ __forceinline__ void layer_mmas(
    float (*d)[4], int l, int tid, int lane, uint32_t sb,
    uint32_t aHiAddr, uint32_t aLoAddr)
{
    for (int kc = 0; kc < NKC; ++kc) {
        const int st = l * NKC + kc;
        CP_WAIT2();
        __syncthreads();

        uint32_t ahi[4], alo[4];
        ldsm4(ahi, aHiAddr + kc * 32);
        ldsm4(alo, aLoAddr + kc * 32);

        const uint32_t bbase = sb + RING_OFF + (st & 3) * SLAB_B + lane * 16 + NTB * 512;
        #pragma unroll
        for (int nt = 0; nt < NNTW; ++nt) {
            uint4 B = lds128(bbase + nt * 512);
            mma16816(d[nt], ahi, B.x, B.y);   // hi*hi
            mma16816(d[nt], alo, B.x, B.y);   // lo*hi
            mma16816(d[nt], ahi, B.z, B.w);   // hi*lo
        }

        if (st + 3 < NSTAGE) {
            const char* src = reinterpret_cast<const char*>(g_wimg) + (size_t)(st + 3) * SLAB_B;
            uint32_t dst = sb + RING_OFF + ((st + 3) & 3) * SLAB_B;
            for (int c = tid; c < SLAB_B / 16; c += THREADS)
                cp16(dst + c * 16, src + c * 16);
        }
        CP_COMMIT();
    }
    __syncthreads();   // all ldsm reads of this layer's A done before epilogue overwrites A
}

template<int NTB, int NNTW>
__device__ __forceinline__ void epi_store(
    const float (*d)[4], const float* biasL, int wm, int g, int t, uint32_t sb)
{
    const uint32_t off0 = (uint32_t)(wm * 16 + g) * ASTRIDE;
    #pragma unroll
    for (int nt = 0; nt < NNTW; ++nt) {
        int c0 = 8 * (NTB + nt) + 2 * t;
        float b0 = biasL[c0], b1 = biasL[c0 + 1];
        float v0 = fmaxf(d[nt][0] + b0, 0.f), v1 = fmaxf(d[nt][1] + b1, 0.f);
        float v2 = fmaxf(d[nt][2] + b0, 0.f), v3 = fmaxf(d[nt][3] + b1, 0.f);
        uint32_t lw0, lw1;
        uint32_t hw0 = packsplit(v0, v1, lw0);
        uint32_t hw1 = packsplit(v2, v3, lw1);
        uint32_t a0 = off0 + (uint32_t)c0 * 2;
        uint32_t a1 = a0 + 8 * ASTRIDE;
        sts32(sb + AHI_OFF + a0, hw0);
        sts32(sb + ALO_OFF + a0, lw0);
        sts32(sb + AHI_OFF + a1, hw1);
        sts32(sb + ALO_OFF + a1, lw1);
    }
}

template<int NTB, int NNTW>
__device__ __forceinline__ void epi_final(
    const float (*d)[4], const float* biasL, const float* woutS,
    float* zp, int h, int wm, int g, int t)
{
    float z0 = 0.f, z1 = 0.f;
    #pragma unroll
    for (int nt = 0; nt < NNTW; ++nt) {
        int c0 = 8 * (NTB + nt) + 2 * t;
        float b0 = biasL[c0], b1 = biasL[c0 + 1];
        float w0 = woutS[c0], w1 = woutS[c0 + 1];
        z0 = fmaf(fmaxf(d[nt][0] + b0, 0.f), w0, z0);
        z0 = fmaf(fmaxf(d[nt][1] + b1, 0.f), w1, z0);
        z1 = fmaf(fmaxf(d[nt][2] + b0, 0.f), w0, z1);
        z1 = fmaf(fmaxf(d[nt][3] + b1, 0.f), w1, z1);
    }
    z0 += __shfl_xor_sync(0xffffffffu, z0, 1);
    z0 += __shfl_xor_sync(0xffffffffu, z0, 2);
    z1 += __shfl_xor_sync(0xffffffffu, z1, 1);
    z1 += __shfl_xor_sync(0xffffffffu, z1, 2);
    if (t == 0) {
        int rl = wm * 16 + g;
        zp[h * 128 + rl]     = z0;
        zp[h * 128 + rl + 8] = z1;
    }
}

// ---------------- fused GraphConv + MLP + sigmoid ----------------
__global__ void __launch_bounds__(THREADS, 1) k_mlp(
    const float* __restrict__ x,
    const float* __restrict__ w_rel, const float* __restrict__ b_rel,
    const float* __restrict__ w_root,
    const float* __restrict__ w_in,  const float* __restrict__ b_in,
    const float* __restrict__ b_hid,
    const float* __restrict__ w_out, const float* __restrict__ b_out,
    float* __restrict__ out)
{
    extern __shared__ char smem[];
    const uint32_t sb = s2u(smem);
    const int tid  = threadIdx.x;
    const int warp = tid >> 5;
    const int lane = tid & 31;
    const int h    = warp >> 3;        // n-half: 0 -> tiles 0..12, 1 -> tiles 13..24
    const int wm   = warp & 7;         // row block: rows wm*16..wm*16+15
    const int g    = lane >> 2;
    const int t    = lane & 3;
    const int row0 = blockIdx.x * TM;

    float* biasS = reinterpret_cast<float*>(smem + BIAS_OFF);   // [6][200]
    float* woutS = reinterpret_cast<float*>(smem + WOUT_OFF);
    float* h0S   = reinterpret_cast<float*>(smem + H0_OFF);
    float* zp    = reinterpret_cast<float*>(smem + ZP_OFF);

    // stage small vectors + h0
    if (tid < HIDDEN) woutS[tid] = __ldg(w_out + tid);
    for (int i = tid; i < NHID * HIDDEN; i += THREADS) biasS[i] = __ldg(b_hid + i);
    if (tid < TM) {
        int r = row0 + tid;
        float a  = (r < N_NODES) ? g_agg[r] : 0.0f;
        float xv = (r < N_NODES) ? __ldg(x + r) : 0.0f;
        h0S[tid] = a * __ldg(w_rel) + __ldg(b_rel) + xv * __ldg(w_root);
    }
    __syncthreads();

    // layer-1 activations (rank-1): A[r][k] = relu(h0[r]*w_in[k]+b_in[k]), k>=200 -> 0
    for (int i = tid; i < TM * 208; i += THREADS) {
        int r = i / 208, k = i - r * 208;
        float v = 0.0f;
        if (k < HIDDEN) v = fmaxf(fmaf(h0S[r], __ldg(w_in + k), __ldg(b_in + k)), 0.0f);
        __nv_bfloat16 hb = __float2bfloat16(v);
        __nv_bfloat16 lb = __float2bfloat16(v - __bfloat162float(hb));
        *reinterpret_cast<__nv_bfloat16*>(smem + AHI_OFF + r * ASTRIDE + k * 2) = hb;
        *reinterpret_cast<__nv_bfloat16*>(smem + ALO_OFF + r * ASTRIDE + k * 2) = lb;
    }

    // prefetch weight slabs 0..2
    #pragma unroll
    for (int ps = 0; ps < 3; ++ps) {
        const char* src = reinterpret_cast<const char*>(g_wimg) + (size_t)ps * SLAB_B;
        uint32_t dst = sb + RING_OFF + ps * SLAB_B;
        for (int c = tid; c < SLAB_B / 16; c += THREADS)
            cp16(dst + c * 16, src + c * 16);
        CP_COMMIT();
    }

    // ldmatrix per-lane address (rows wm*16 .. +15)
    const int lrow = lane & 15;
    const uint32_t aHiAddr = sb + AHI_OFF + (wm * 16 + lrow) * ASTRIDE + (lane >> 4) * 16;
    const uint32_t aLoAddr = sb + ALO_OFF + (wm * 16 + lrow) * ASTRIDE + (lane >> 4) * 16;

    float d[13][4];

    for (int l = 0; l < NHID; ++l) {
        #pragma unroll
        for (int nt = 0; nt < 13; ++nt) {
            d[nt][0] = 0.f; d[nt][1] = 0.f; d[nt][2] = 0.f; d[nt][3] = 0.f;
        }

        if (h == 0) layer_mmas<0, 13>(d, l, tid, lane, sb, aHiAddr, aLoAddr);
        else        layer_mmas<13, 12>(d, l, tid, lane, sb, aHiAddr, aLoAddr);

        const float* biasL = biasS + l * HIDDEN;
        if (l < NHID - 1) {
            if (h == 0) epi_store<0, 13>(d, biasL, wm, g, t, sb);
            else        epi_store<13, 12>(d, biasL, wm, g, t, sb);
        } else {
            if (h == 0) epi_final<0, 13>(d, biasL, woutS, zp, h, wm, g, t);
            else        epi_final<13, 12>(d, biasL, woutS, zp, h, wm, g, t);
        }
    }

    __syncthreads();
    if (tid < TM) {
        int r = row0 + tid;
        if (r < N_NODES) {
            float z = zp[tid] + zp[128 + tid] + __ldg(b_out);
            out[r] = 1.0f / (1.0f + expf(-z));
        }
    }
}

// ---------------- launch ----------------
extern "C" void kernel_launch(void* const* d_in, const int* in_sizes, int n_in,
                              void* d_out, int out_size)
{
    const float* x      = (const float*)d_in[0];
    const int*   ei     = (const int*)d_in[1];      // int32 (jax x64 disabled)
    const float* w_rel  = (const float*)d_in[2];
    const float* b_rel  = (const float*)d_in[3];
    const float* w_root = (const float*)d_in[4];
    const float* w_in   = (const float*)d_in[5];
    const float* b_in   = (const float*)d_in[6];
    const float* w_hid  = (const float*)d_in[7];
    const float* b_hid  = (const float*)d_in[8];
    const float* w_out  = (const float*)d_in[9];
    const float* b_out  = (const float*)d_in[10];
    float*       out    = (float*)d_out;

    cudaFuncSetAttribute(k_mlp, cudaFuncAttributeMaxDynamicSharedMemorySize, SMEM_BYTES);

    k_prep<<<(NHID * NKC * NNT * 32 + 255) / 256, 256>>>(w_hid);
    k_zero<<<(N_NODES + 255) / 256, 256>>>();
    k_scatter<<<(N_EDGES / 4 + 255) / 256, 256>>>(x, ei);
    k_mlp<<<NCTA, THREADS, SMEM_BYTES>>>(
        x, w_rel, b_rel, w_root, w_in, b_in, b_hid, w_out, b_out, out);
}

// round 7
// speedup vs baseline: 1.3330x; 1.3330x over previous
#include <cuda_runtime.h>
#include <cuda_bf16.h>
#include <cstdint>

#define N_NODES 200000
#define N_EDGES 6400000
#define HIDDEN  200
#define NHID    6
#define TM      64
#define THREADS 256
#define NCTA    ((N_NODES + TM - 1) / TM)   // 3125

#define NKC     13                  // k16 chunks (K=200 padded to 208)
#define NNT     25                  // n8 tiles (N=200)
#define NSTAGE  (NHID * NKC)        // 78
#define SLAB_B  (NNT * 32 * 16)     // 12800 bytes per (layer,kc) weight slab
#define ASTRIDE 432                 // bytes per activation row (216 bf16)

// smem offsets (bytes) — total 112864, 2 CTAs/SM
#define RING_OFF 0                  // 4 x SLAB_B = 51200
#define AHI_OFF  51200              // 64 x 432 = 27648
#define ALO_OFF  78848              // 27648
#define BIAS_OFF 106496             // 6*200 f32 = 4800
#define WOUT_OFF 111296             // 200 f32 = 800
#define H0_OFF   112096             // 64 f32 = 256
#define ZP_OFF   112352             // 2*64 f32 = 512
#define SMEM_BYTES 112864

__device__ float g_agg[N_NODES];
__device__ __align__(16) uint4 g_wimg[NHID * NKC * NNT * 32];   // 998400 B

// ---------------- tiny kernels ----------------
__global__ void k_zero() {
    int i = blockIdx.x * blockDim.x + threadIdx.x;
    if (i < N_NODES) g_agg[i] = 0.0f;
}

__global__ void k_scatter(const float* __restrict__ x, const int* __restrict__ ei) {
    int i = blockIdx.x * blockDim.x + threadIdx.x;
    if (i < N_EDGES / 4) {
        const int4 s = reinterpret_cast<const int4*>(ei)[i];
        const int4 d = reinterpret_cast<const int4*>(ei + N_EDGES)[i];
        atomicAdd(&g_agg[d.x], x[s.x]);
        atomicAdd(&g_agg[d.y], x[s.y]);
        atomicAdd(&g_agg[d.z], x[s.z]);
        atomicAdd(&g_agg[d.w], x[s.w]);
    }
}

__device__ __forceinline__ uint32_t packsplit(float v0, float v1, uint32_t& lo) {
    __nv_bfloat16 h0 = __float2bfloat16(v0), h1 = __float2bfloat16(v1);
    float f0 = __bfloat162float(h0), f1 = __bfloat162float(h1);
    __nv_bfloat16 l0 = __float2bfloat16(v0 - f0), l1 = __float2bfloat16(v1 - f1);
    lo = ((uint32_t)__bfloat16_as_ushort(l1) << 16) | (uint32_t)__bfloat16_as_ushort(l0);
    return ((uint32_t)__bfloat16_as_ushort(h1) << 16) | (uint32_t)__bfloat16_as_ushort(h0);
}

// Pack w_hid into per-lane mma B-fragment order:
// idx = ((l*13+kc)*25+nt)*32 + lane -> uint4 {b0hi, b1hi, b0lo, b1lo}
__global__ void k_prep(const float* __restrict__ w_hid) {
    int idx = blockIdx.x * blockDim.x + threadIdx.x;
    if (idx >= NHID * NKC * NNT * 32) return;
    int lane = idx & 31;
    int u = idx >> 5;
    int nt = u % NNT; u /= NNT;
    int kc = u % NKC; int l = u / NKC;
    int t = lane & 3, g = lane >> 2;
    int n = nt * 8 + g;
    int k0 = kc * 16 + t * 2;
    float w00 = (k0     < HIDDEN) ? w_hid[((size_t)l * HIDDEN + k0    ) * HIDDEN + n] : 0.f;
    float w01 = (k0 + 1 < HIDDEN) ? w_hid[((size_t)l * HIDDEN + k0 + 1) * HIDDEN + n] : 0.f;
    float w10 = (k0 + 8 < HIDDEN) ? w_hid[((size_t)l * HIDDEN + k0 + 8) * HIDDEN + n] : 0.f;
    float w11 = (k0 + 9 < HIDDEN) ? w_hid[((size_t)l * HIDDEN + k0 + 9) * HIDDEN + n] : 0.f;
    uint4 v;
    uint32_t lo0, lo1;
    v.x = packsplit(w00, w01, lo0);
    v.y = packsplit(w10, w11, lo1);
    v.z = lo0;
    v.w = lo1;
    g_wimg[idx] = v;
}

// ---------------- asm helpers ----------------
__device__ __forceinline__ uint32_t s2u(const void* p) {
    uint32_t a;
    asm("{ .reg .u64 t; cvta.to.shared.u64 t, %1; cvt.u32.u64 %0, t; }" : "=r"(a) : "l"(p));
    return a;
}
__device__ __forceinline__ void cp16(uint32_t sdst, const void* gsrc) {
    asm volatile("cp.async.cg.shared.global [%0], [%1], 16;" :: "r"(sdst), "l"(gsrc));
}
#define CP_COMMIT() asm volatile("cp.async.commit_group;")
#define CP_WAIT2()  asm volatile("cp.async.wait_group 2;")

__device__ __forceinline__ void ldsm4(uint32_t* r, uint32_t a) {
    asm volatile("ldmatrix.sync.aligned.m8n8.x4.shared.b16 {%0,%1,%2,%3}, [%4];"
        : "=r"(r[0]), "=r"(r[1]), "=r"(r[2]), "=r"(r[3]) : "r"(a));
}
__device__ __forceinline__ uint4 lds128(uint32_t a) {
    uint4 v;
    asm volatile("ld.shared.v4.u32 {%0,%1,%2,%3}, [%4];"
        : "=r"(v.x), "=r"(v.y), "=r"(v.z), "=r"(v.w) : "r"(a));
    return v;
}
__device__ __forceinline__ void sts32(uint32_t a, uint32_t v) {
    asm volatile("st.shared.u32 [%0], %1;" :: "r"(a), "r"(v));
}
__device__ __forceinline__ void mma16816(float* d, const uint32_t* a, uint32_t b0, uint32_t b1) {
    asm volatile("mma.sync.aligned.m16n8k16.row.col.f32.bf16.bf16.f32 "
        "{%0,%1,%2,%3}, {%4,%5,%6,%7}, {%8,%9}, {%0,%1,%2,%3};"
        : "+f"(d[0]), "+f"(d[1]), "+f"(d[2]), "+f"(d[3])
        : "r"(a[0]), "r"(a[1]), "r"(a[2]), "r"(a[3]), "r"(b0), "r"(b1));
}

// ---------------- templated layer MMA loop ----------------
template<int NTB, int NNTW>
__device__ __forceinline__ void layer_mmas(
    float (*d)[4], int l, int tid, int lane, uint32_t sb,
    uint32_t aHiAddr, uint32_t aLoAddr)
{
    for (int kc = 0; kc < NKC; ++kc) {
        const int st = l * NKC + kc;
        CP_WAIT2();
        __syncthreads();

        uint32_t ahi[4], alo[4];
        ldsm4(ahi, aHiAddr + kc * 32);
        ldsm4(alo, aLoAddr + kc * 32);

        // issue next prefetch FIRST so cp.async overlaps the MMA burst
        if (st + 3 < NSTAGE) {
            const char* src = reinterpret_cast<const char*>(g_wimg) + (size_t)(st + 3) * SLAB_B;
            uint32_t dst = sb + RING_OFF + ((st + 3) & 3) * SLAB_B;
            #pragma unroll
            for (int c = 0; c < (SLAB_B / 16 + THREADS - 1) / THREADS; ++c) {
                int idx = tid + c * THREADS;
                if (idx < SLAB_B / 16) cp16(dst + idx * 16, src + idx * 16);
            }
        }
        CP_COMMIT();

        const uint32_t bbase = sb + RING_OFF + (st & 3) * SLAB_B + lane * 16 + NTB * 512;
        #pragma unroll
        for (int nt = 0; nt < NNTW; ++nt) {
            uint4 B = lds128(bbase + nt * 512);
            mma16816(d[nt], ahi, B.x, B.y);   // hi*hi
            mma16816(d[nt], alo, B.x, B.y);   // lo*hi
            mma16816(d[nt], ahi, B.z, B.w);   // hi*lo
        }
    }
    __syncthreads();   // all ldsm reads of this layer's A done before epilogue overwrites A
}

template<int NTB, int NNTW>
__device__ __forceinline__ void epi_store(
    const float (*d)[4], const float* biasL, int wm, int g, int t, uint32_t sb)
{
    const uint32_t off0 = (uint32_t)(wm * 16 + g) * ASTRIDE;
    #pragma unroll
    for (int nt = 0; nt < NNTW; ++nt) {
        int c0 = 8 * (NTB + nt) + 2 * t;
        float b0 = biasL[c0], b1 = biasL[c0 + 1];
        float v0 = fmaxf(d[nt][0] + b0, 0.f), v1 = fmaxf(d[nt][1] + b1, 0.f);
        float v2 = fmaxf(d[nt][2] + b0, 0.f), v3 = fmaxf(d[nt][3] + b1, 0.f);
        uint32_t lw0, lw1;
        uint32_t hw0 = packsplit(v0, v1, lw0);
        uint32_t hw1 = packsplit(v2, v3, lw1);
        uint32_t a0 = off0 + (uint32_t)c0 * 2;
        uint32_t a1 = a0 + 8 * ASTRIDE;
        sts32(sb + AHI_OFF + a0, hw0);
        sts32(sb + ALO_OFF + a0, lw0);
        sts32(sb + AHI_OFF + a1, hw1);
        sts32(sb + ALO_OFF + a1, lw1);
    }
}

template<int NTB, int NNTW>
__device__ __forceinline__ void epi_final(
    const float (*d)[4], const float* biasL, const float* woutS,
    float* zp, int h, int wm, int g, int t)
{
    float z0 = 0.f, z1 = 0.f;
    #pragma unroll
    for (int nt = 0; nt < NNTW; ++nt) {
        int c0 = 8 * (NTB + nt) + 2 * t;
        float b0 = biasL[c0], b1 = biasL[c0 + 1];
        float w0 = woutS[c0], w1 = woutS[c0 + 1];
        z0 = fmaf(fmaxf(d[nt][0] + b0, 0.f), w0, z0);
        z0 = fmaf(fmaxf(d[nt][1] + b1, 0.f), w1, z0);
        z1 = fmaf(fmaxf(d[nt][2] + b0, 0.f), w0, z1);
        z1 = fmaf(fmaxf(d[nt][3] + b1, 0.f), w1, z1);
    }
    z0 += __shfl_xor_sync(0xffffffffu, z0, 1);
    z0 += __shfl_xor_sync(0xffffffffu, z0, 2);
    z1 += __shfl_xor_sync(0xffffffffu, z1, 1);
    z1 += __shfl_xor_sync(0xffffffffu, z1, 2);
    if (t == 0) {
        int rl = wm * 16 + g;
        zp[h * TM + rl]     = z0;
        zp[h * TM + rl + 8] = z1;
    }
}

// ---------------- fused GraphConv + MLP + sigmoid ----------------
__global__ void __launch_bounds__(THREADS, 2) k_mlp(
    const float* __restrict__ x,
    const float* __restrict__ w_rel, const float* __restrict__ b_rel,
    const float* __restrict__ w_root,
    const float* __restrict__ w_in,  const float* __restrict__ b_in,
    const float* __restrict__ b_hid,
    const float* __restrict__ w_out, const float* __restrict__ b_out,
    float* __restrict__ out)
{
    extern __shared__ char smem[];
    const uint32_t sb = s2u(smem);
    const int tid  = threadIdx.x;
    const int warp = tid >> 5;
    const int lane = tid & 31;
    const int h    = warp >> 2;        // n-half: 0 -> tiles 0..12, 1 -> tiles 13..24
    const int wm   = warp & 3;         // row block: rows wm*16..wm*16+15
    const int g    = lane >> 2;
    const int t    = lane & 3;
    const int row0 = blockIdx.x * TM;

    float* biasS = reinterpret_cast<float*>(smem + BIAS_OFF);   // [6][200]
    float* woutS = reinterpret_cast<float*>(smem + WOUT_OFF);
    float* h0S   = reinterpret_cast<float*>(smem + H0_OFF);
    float* zp    = reinterpret_cast<float*>(smem + ZP_OFF);

    // stage small vectors + h0
    if (tid < HIDDEN) woutS[tid] = __ldg(w_out + tid);
    for (int i = tid; i < NHID * HIDDEN; i += THREADS) biasS[i] = __ldg(b_hid + i);
    if (tid < TM) {
        int r = row0 + tid;
        float a  = (r < N_NODES) ? g_agg[r] : 0.0f;
        float xv = (r < N_NODES) ? __ldg(x + r) : 0.0f;
        h0S[tid] = a * __ldg(w_rel) + __ldg(b_rel) + xv * __ldg(w_root);
    }
    __syncthreads();

    // layer-1 activations (rank-1): A[r][k] = relu(h0[r]*w_in[k]+b_in[k]), k>=200 -> 0
    for (int i = tid; i < TM * 208; i += THREADS) {
        int r = i / 208, k = i - r * 208;
        float v = 0.0f;
        if (k < HIDDEN) v = fmaxf(fmaf(h0S[r], __ldg(w_in + k), __ldg(b_in + k)), 0.0f);
        __nv_bfloat16 hb = __float2bfloat16(v);
        __nv_bfloat16 lb = __float2bfloat16(v - __bfloat162float(hb));
        *reinterpret_cast<__nv_bfloat16*>(smem + AHI_OFF + r * ASTRIDE + k * 2) = hb;
        *reinterpret_cast<__nv_bfloat16*>(smem + ALO_OFF + r * ASTRIDE + k * 2) = lb;
    }

    // prefetch weight slabs 0..2
    #pragma unroll
    for (int ps = 0; ps < 3; ++ps) {
        const char* src = reinterpret_cast<const char*>(g_wimg) + (size_t)ps * SLAB_B;
        uint32_t dst = sb + RING_OFF + ps * SLAB_B;
        for (int c = tid; c < SLAB_B / 16; c += THREADS)
            cp16(dst + c * 16, src + c * 16);
        CP_COMMIT();
    }

    // ldmatrix per-lane address (rows wm*16 .. +15)
    const int lrow = lane & 15;
    const uint32_t aHiAddr = sb + AHI_OFF + (wm * 16 + lrow) * ASTRIDE + (lane >> 4) * 16;
    const uint32_t aLoAddr = sb + ALO_OFF + (wm * 16 + lrow) * ASTRIDE + (lane >> 4) * 16;

    float d[13][4];

    for (int l = 0; l < NHID; ++l) {
        #pragma unroll
        for (int nt = 0; nt < 13; ++nt) {
            d[nt][0] = 0.f; d[nt][1] = 0.f; d[nt][2] = 0.f; d[nt][3] = 0.f;
        }

        if (h == 0) layer_mmas<0, 13>(d, l, tid, lane, sb, aHiAddr, aLoAddr);
        else        layer_mmas<13, 12>(d, l, tid, lane, sb, aHiAddr, aLoAddr);

        const float* biasL = biasS + l * HIDDEN;
        if (l < NHID - 1) {
            if (h == 0) epi_store<0, 13>(d, biasL, wm, g, t, sb);
            else        epi_store<13, 12>(d, biasL, wm, g, t, sb);
        } else {
            if (h == 0) epi_final<0, 13>(d, biasL, woutS, zp, h, wm, g, t);
            else        epi_final<13, 12>(d, biasL, woutS, zp, h, wm, g, t);
        }
    }

    __syncthreads();
    if (tid < TM) {
        int r = row0 + tid;
        if (r < N_NODES) {
            float z = zp[tid] + zp[TM + tid] + __ldg(b_out);
            out[r] = 1.0f / (1.0f + expf(-z));
        }
    }
}

// ---------------- launch ----------------
extern "C" void kernel_launch(void* const* d_in, const int* in_sizes, int n_in,
                              void* d_out, int out_size)
{
    const float* x      = (const float*)d_in[0];
    const int*   ei     = (const int*)d_in[1];      // int32 (jax x64 disabled)
    const float* w_rel  = (const float*)d_in[2];
    const float* b_rel  = (const float*)d_in[3];
    const float* w_root = (const float*)d_in[4];
    const float* w_in   = (const float*)d_in[5];
    const float* b_in   = (const float*)d_in[6];
    const float* w_hid  = (const float*)d_in[7];
    const float* b_hid  = (const float*)d_in[8];
    const float* w_out  = (const float*)d_in[9];
    const float* b_out  = (const float*)d_in[10];
    float*       out    = (float*)d_out;

    cudaFuncSetAttribute(k_mlp, cudaFuncAttributeMaxDynamicSharedMemorySize, SMEM_BYTES);

    k_prep<<<(NHID * NKC * NNT * 32 + 255) / 256, 256>>>(w_hid);
    k_zero<<<(N_NODES + 255) / 256, 256>>>();
    k_scatter<<<(N_EDGES / 4 + 255) / 256, 256>>>(x, ei);
    k_mlp<<<NCTA, THREADS, SMEM_BYTES>>>(
        x, w_rel, b_rel, w_root, w_in, b_in, b_hid, w_out, b_out, out);
}

// round 8
// speedup vs baseline: 1.9231x; 1.4427x over previous
#include <cuda_runtime.h>
#include <cuda_fp16.h>
#include <cstdint>

#define N_NODES 200000
#define N_EDGES 6400000
#define HIDDEN  200
#define NHID    6
#define TM      64
#define THREADS 256
#define NCTA    ((N_NODES + TM - 1) / TM)   // 3125

#define NKC     13                  // k16 chunks (K=200 padded to 208)
#define NNT     25                  // n8 tiles (N=200)
#define NSTAGE  (NHID * NKC)        // 78
#define SLAB_B  (NNT * 32 * 8)      // 6400 bytes per (layer,kc) weight slab (fp16 single)
#define ASTRIDE 432                 // bytes per activation row (216 fp16)

// smem offsets (bytes) — total 87264, 2 CTAs/SM
#define RING_OFF 0                  // 4 x SLAB_B = 25600
#define AHI_OFF  25600              // 64 x 432 = 27648
#define ALO_OFF  53248              // 27648
#define BIAS_OFF 80896              // 6*200 f32 = 4800
#define WOUT_OFF 85696              // 200 f32 = 800
#define H0_OFF   86496              // 64 f32 = 256
#define ZP_OFF   86752              // 2*64 f32 = 512
#define SMEM_BYTES 87264

__device__ float g_agg[N_NODES];
__device__ __align__(16) uint2 g_wimg[NHID * NKC * NNT * 32];   // 499200 B

// ---------------- tiny kernels ----------------
__global__ void k_zero() {
    int i = blockIdx.x * blockDim.x + threadIdx.x;
    if (i < N_NODES) g_agg[i] = 0.0f;
}

__global__ void k_scatter(const float* __restrict__ x, const int* __restrict__ ei) {
    int i = blockIdx.x * blockDim.x + threadIdx.x;
    if (i < N_EDGES / 4) {
        const int4 s = reinterpret_cast<const int4*>(ei)[i];
        const int4 d = reinterpret_cast<const int4*>(ei + N_EDGES)[i];
        atomicAdd(&g_agg[d.x], x[s.x]);
        atomicAdd(&g_agg[d.y], x[s.y]);
        atomicAdd(&g_agg[d.z], x[s.z]);
        atomicAdd(&g_agg[d.w], x[s.w]);
    }
}

__device__ __forceinline__ uint32_t packh2(float v0, float v1) {
    __half2 h = __floats2half2_rn(v0, v1);
    return *reinterpret_cast<uint32_t*>(&h);
}
// fp16 hi/lo split of a value pair
__device__ __forceinline__ uint32_t packsplit(float v0, float v1, uint32_t& lo) {
    __half h0 = __float2half_rn(v0), h1 = __float2half_rn(v1);
    float f0 = __half2float(h0), f1 = __half2float(h1);
    lo = packh2(v0 - f0, v1 - f1);
    return ((uint32_t)__half_as_ushort(h1) << 16) | (uint32_t)__half_as_ushort(h0);
}

// Pack w_hid into per-lane mma B-fragment order (single fp16):
// idx = ((l*13+kc)*25+nt)*32 + lane -> uint2 {b0, b1}
// b0 holds W[k=16kc+2t+{0,1}, n=8nt+g], b1 holds k+8 pair. (t=lane&3, g=lane>>2)
__global__ void k_prep(const float* __restrict__ w_hid) {
    int idx = blockIdx.x * blockDim.x + threadIdx.x;
    if (idx >= NHID * NKC * NNT * 32) return;
    int lane = idx & 31;
    int u = idx >> 5;
    int nt = u % NNT; u /= NNT;
    int kc = u % NKC; int l = u / NKC;
    int t = lane & 3, g = lane >> 2;
    int n = nt * 8 + g;
    int k0 = kc * 16 + t * 2;
    float w00 = (k0     < HIDDEN) ? w_hid[((size_t)l * HIDDEN + k0    ) * HIDDEN + n] : 0.f;
    float w01 = (k0 + 1 < HIDDEN) ? w_hid[((size_t)l * HIDDEN + k0 + 1) * HIDDEN + n] : 0.f;
    float w10 = (k0 + 8 < HIDDEN) ? w_hid[((size_t)l * HIDDEN + k0 + 8) * HIDDEN + n] : 0.f;
    float w11 = (k0 + 9 < HIDDEN) ? w_hid[((size_t)l * HIDDEN + k0 + 9) * HIDDEN + n] : 0.f;
    uint2 v;
    v.x = packh2(w00, w01);
    v.y = packh2(w10, w11);
    g_wimg[idx] = v;
}

// ---------------- asm helpers ----------------
__device__ __forceinline__ uint32_t s2u(const void* p) {
    uint32_t a;
    asm("{ .reg .u64 t; cvta.to.shared.u64 t, %1; cvt.u32.u64 %0, t; }" : "=r"(a) : "l"(p));
    return a;
}
__device__ __forceinline__ void cp16(uint32_t sdst, const void* gsrc) {
    asm volatile("cp.async.cg.shared.global [%0], [%1], 16;" :: "r"(sdst), "l"(gsrc));
}
#define CP_COMMIT() asm volatile("cp.async.commit_group;")
#define CP_WAIT2()  asm volatile("cp.async.wait_group 2;")

__device__ __forceinline__ void ldsm4(uint32_t* r, uint32_t a) {
    asm volatile("ldmatrix.sync.aligned.m8n8.x4.shared.b16 {%0,%1,%2,%3}, [%4];"
        : "=r"(r[0]), "=r"(r[1]), "=r"(r[2]), "=r"(r[3]) : "r"(a));
}
__device__ __forceinline__ uint2 lds64(uint32_t a) {
    uint2 v;
    asm volatile("ld.shared.v2.u32 {%0,%1}, [%2];" : "=r"(v.x), "=r"(v.y) : "r"(a));
    return v;
}
__device__ __forceinline__ void sts32(uint32_t a, uint32_t v) {
    asm volatile("st.shared.u32 [%0], %1;" :: "r"(a), "r"(v));
}
__device__ __forceinline__ void mma16816(float* d, const uint32_t* a, uint32_t b0, uint32_t b1) {
    asm volatile("mma.sync.aligned.m16n8k16.row.col.f32.f16.f16.f32 "
        "{%0,%1,%2,%3}, {%4,%5,%6,%7}, {%8,%9}, {%0,%1,%2,%3};"
        : "+f"(d[0]), "+f"(d[1]), "+f"(d[2]), "+f"(d[3])
        : "r"(a[0]), "r"(a[1]), "r"(a[2]), "r"(a[3]), "r"(b0), "r"(b1));
}

// ---------------- templated layer MMA loop ----------------
template<int NTB, int NNTW>
__device__ __forceinline__ void layer_mmas(
    float (*d)[4], int l, int tid, int lane, uint32_t sb,
    uint32_t aHiAddr, uint32_t aLoAddr)
{
    for (int kc = 0; kc < NKC; ++kc) {
        const int st = l * NKC + kc;
        CP_WAIT2();
        __syncthreads();

        uint32_t ahi[4], alo[4];
        ldsm4(ahi, aHiAddr + kc * 32);
        ldsm4(alo, aLoAddr + kc * 32);

        // issue next prefetch FIRST so cp.async overlaps the MMA burst
        if (st + 3 < NSTAGE) {
            const char* src = reinterpret_cast<const char*>(g_wimg) + (size_t)(st + 3) * SLAB_B;
            uint32_t dst = sb + RING_OFF + ((st + 3) & 3) * SLAB_B;
            #pragma unroll
            for (int c = 0; c < (SLAB_B / 16 + THREADS - 1) / THREADS; ++c) {
                int idx = tid + c * THREADS;
                if (idx < SLAB_B / 16) cp16(dst + idx * 16, src + idx * 16);
            }
        }
        CP_COMMIT();

        const uint32_t bbase = sb + RING_OFF + (st & 3) * SLAB_B + lane * 8 + NTB * 256;
        #pragma unroll
        for (int nt = 0; nt < NNTW; ++nt) {
            uint2 B = lds64(bbase + nt * 256);
            mma16816(d[nt], ahi, B.x, B.y);   // hi * B
            mma16816(d[nt], alo, B.x, B.y);   // lo * B
        }
    }
    __syncthreads();   // all ldsm reads of this layer's A done before epilogue overwrites A
}

template<int NTB, int NNTW>
__device__ __forceinline__ void epi_store(
    const float (*d)[4], const float* biasL, int wm, int g, int t, uint32_t sb)
{
    const uint32_t off0 = (uint32_t)(wm * 16 + g) * ASTRIDE;
    #pragma unroll
    for (int nt = 0; nt < NNTW; ++nt) {
        int c0 = 8 * (NTB + nt) + 2 * t;
        float b0 = biasL[c0], b1 = biasL[c0 + 1];
        float v0 = fmaxf(d[nt][0] + b0, 0.f), v1 = fmaxf(d[nt][1] + b1, 0.f);
        float v2 = fmaxf(d[nt][2] + b0, 0.f), v3 = fmaxf(d[nt][3] + b1, 0.f);
        uint32_t lw0, lw1;
        uint32_t hw0 = packsplit(v0, v1, lw0);
        uint32_t hw1 = packsplit(v2, v3, lw1);
        uint32_t a0 = off0 + (uint32_t)c0 * 2;
        uint32_t a1 = a0 + 8 * ASTRIDE;
        sts32(sb + AHI_OFF + a0, hw0);
        sts32(sb + ALO_OFF + a0, lw0);
        sts32(sb + AHI_OFF + a1, hw1);
        sts32(sb + ALO_OFF + a1, lw1);
    }
}

template<int NTB, int NNTW>
__device__ __forceinline__ void epi_final(
    const float (*d)[4], const float* biasL, const float* woutS,
    float* zp, int h, int wm, int g, int t)
{
    float z0 = 0.f, z1 = 0.f;
    #pragma unroll
    for (int nt = 0; nt < NNTW; ++nt) {
        int c0 = 8 * (NTB + nt) + 2 * t;
        float b0 = biasL[c0], b1 = biasL[c0 + 1];
        float w0 = woutS[c0], w1 = woutS[c0 + 1];
        z0 = fmaf(fmaxf(d[nt][0] + b0, 0.f), w0, z0);
        z0 = fmaf(fmaxf(d[nt][1] + b1, 0.f), w1, z0);
        z1 = fmaf(fmaxf(d[nt][2] + b0, 0.f), w0, z1);
        z1 = fmaf(fmaxf(d[nt][3] + b1, 0.f), w1, z1);
    }
    z0 += __shfl_xor_sync(0xffffffffu, z0, 1);
    z0 += __shfl_xor_sync(0xffffffffu, z0, 2);
    z1 += __shfl_xor_sync(0xffffffffu, z1, 1);
    z1 += __shfl_xor_sync(0xffffffffu, z1, 2);
    if (t == 0) {
        int rl = wm * 16 + g;
        zp[h * TM + rl]     = z0;
        zp[h * TM + rl + 8] = z1;
    }
}

// ---------------- fused GraphConv + MLP + sigmoid ----------------
__global__ void __launch_bounds__(THREADS, 2) k_mlp(
    const float* __restrict__ x,
    const float* __restrict__ w_rel, const float* __restrict__ b_rel,
    const float* __restrict__ w_root,
    const float* __restrict__ w_in,  const float* __restrict__ b_in,
    const float* __restrict__ b_hid,
    const float* __restrict__ w_out, const float* __restrict__ b_out,
    float* __restrict__ out)
{
    extern __shared__ char smem[];
    const uint32_t sb = s2u(smem);
    const int tid  = threadIdx.x;
    const int warp = tid >> 5;
    const int lane = tid & 31;
    const int h    = warp >> 2;        // n-half: 0 -> tiles 0..12, 1 -> tiles 13..24
    const int wm   = warp & 3;         // row block: rows wm*16..wm*16+15
    const int g    = lane >> 2;
    const int t    = lane & 3;
    const int row0 = blockIdx.x * TM;

    float* biasS = reinterpret_cast<float*>(smem + BIAS_OFF);   // [6][200]
    float* woutS = reinterpret_cast<float*>(smem + WOUT_OFF);
    float* h0S   = reinterpret_cast<float*>(smem + H0_OFF);
    float* zp    = reinterpret_cast<float*>(smem + ZP_OFF);

    // stage small vectors + h0
    if (tid < HIDDEN) woutS[tid] = __ldg(w_out + tid);
    for (int i = tid; i < NHID * HIDDEN; i += THREADS) biasS[i] = __ldg(b_hid + i);
    if (tid < TM) {
        int r = row0 + tid;
        float a  = (r < N_NODES) ? g_agg[r] : 0.0f;
        float xv = (r < N_NODES) ? __ldg(x + r) : 0.0f;
        h0S[tid] = a * __ldg(w_rel) + __ldg(b_rel) + xv * __ldg(w_root);
    }
    __syncthreads();

    // layer-1 activations (rank-1): A[r][k] = relu(h0[r]*w_in[k]+b_in[k]), k>=200 -> 0
    for (int i = tid; i < TM * 208; i += THREADS) {
        int r = i / 208, k = i - r * 208;
        float v = 0.0f;
        if (k < HIDDEN) v = fmaxf(fmaf(h0S[r], __ldg(w_in + k), __ldg(b_in + k)), 0.0f);
        __half hb = __float2half_rn(v);
        __half lb = __float2half_rn(v - __half2float(hb));
        *reinterpret_cast<__half*>(smem + AHI_OFF + r * ASTRIDE + k * 2) = hb;
        *reinterpret_cast<__half*>(smem + ALO_OFF + r * ASTRIDE + k * 2) = lb;
    }

    // prefetch weight slabs 0..2
    #pragma unroll
    for (int ps = 0; ps < 3; ++ps) {
        const char* src = reinterpret_cast<const char*>(g_wimg) + (size_t)ps * SLAB_B;
        uint32_t dst = sb + RING_OFF + ps * SLAB_B;
        for (int c = tid; c < SLAB_B / 16; c += THREADS)
            cp16(dst + c * 16, src + c * 16);
        CP_COMMIT();
    }

    // ldmatrix per-lane address (rows wm*16 .. +15)
    const int lrow = lane & 15;
    const uint32_t aHiAddr = sb + AHI_OFF + (wm * 16 + lrow) * ASTRIDE + (lane >> 4) * 16;
    const uint32_t aLoAddr = sb + ALO_OFF + (wm * 16 + lrow) * ASTRIDE + (lane >> 4) * 16;

    float d[13][4];

    for (int l = 0; l < NHID; ++l) {
        #pragma unroll
        for (int nt = 0; nt < 13; ++nt) {
            d[nt][0] = 0.f; d[nt][1] = 0.f; d[nt][2] = 0.f; d[nt][3] = 0.f;
        }

        if (h == 0) layer_mmas<0, 13>(d, l, tid, lane, sb, aHiAddr, aLoAddr);
        else        layer_mmas<13, 12>(d, l, tid, lane, sb, aHiAddr, aLoAddr);

        const float* biasL = biasS + l * HIDDEN;
        if (l < NHID - 1) {
            if (h == 0) epi_store<0, 13>(d, biasL, wm, g, t, sb);
            else        epi_store<13, 12>(d, biasL, wm, g, t, sb);
        } else {
            if (h == 0) epi_final<0, 13>(d, biasL, woutS, zp, h, wm, g, t);
            else        epi_final<13, 12>(d, biasL, woutS, zp, h, wm, g, t);
        }
    }

    __syncthreads();
    if (tid < TM) {
        int r = row0 + tid;
        if (r < N_NODES) {
            float z = zp[tid] + zp[TM + tid] + __ldg(b_out);
            out[r] = 1.0f / (1.0f + expf(-z));
        }
    }
}

// ---------------- launch ----------------
extern "C" void kernel_launch(void* const* d_in, const int* in_sizes, int n_in,
                              void* d_out, int out_size)
{
    const float* x      = (const float*)d_in[0];
    const int*   ei     = (const int*)d_in[1];      // int32 (jax x64 disabled)
    const float* w_rel  = (const float*)d_in[2];
    const float* b_rel  = (const float*)d_in[3];
    const float* w_root = (const float*)d_in[4];
    const float* w_in   = (const float*)d_in[5];
    const float* b_in   = (const float*)d_in[6];
    const float* w_hid  = (const float*)d_in[7];
    const float* b_hid  = (const float*)d_in[8];
    const float* w_out  = (const float*)d_in[9];
    const float* b_out  = (const float*)d_in[10];
    float*       out    = (float*)d_out;

    cudaFuncSetAttribute(k_mlp, cudaFuncAttributeMaxDynamicSharedMemorySize, SMEM_BYTES);

    k_prep<<<(NHID * NKC * NNT * 32 + 255) / 256, 256>>>(w_hid);
    k_zero<<<(N_NODES + 255) / 256, 256>>>();
    k_scatter<<<(N_EDGES / 4 + 255) / 256, 256>>>(x, ei);
    k_mlp<<<NCTA, THREADS, SMEM_BYTES>>>(
        x, w_rel, b_rel, w_root, w_in, b_in, b_hid, w_out, b_out, out);
}

// round 9
// speedup vs baseline: 2.8248x; 1.4688x over previous
#include <cuda_runtime.h>
#include <cuda_fp16.h>
#include <cstdint>

#define N_NODES 200000
#define N_EDGES 6400000
#define HIDDEN  200
#define NHID    6
#define TM      64
#define THREADS 256
#define NCTA    ((N_NODES + TM - 1) / TM)   // 3125

#define NKC     13                  // k16 chunks (K=200 padded to 208)
#define NNT     25                  // n8 tiles (N=200)
#define NSTAGE  (NHID * NKC)        // 78
#define SLAB_B  (NNT * 32 * 8)      // 6400 bytes per (layer,kc) weight slab (fp16)
#define ASTRIDE 432                 // bytes per activation row (216 fp16)

// smem offsets (bytes) — total 59616, 3 CTAs/SM
#define RING_OFF 0                  // 4 x SLAB_B = 25600
#define A_OFF    25600              // 64 x 432 = 27648
#define BIAS_OFF 53248              // 6*200 f32 = 4800
#define WOUT_OFF 58048              // 200 f32 = 800
#define H0_OFF   58848              // 64 f32 = 256
#define ZP_OFF   59104              // 2*64 f32 = 512
#define SMEM_BYTES 59616

__device__ float g_agg[N_NODES];
__device__ __align__(16) uint2 g_wimg[NHID * NKC * NNT * 32];   // 499200 B

// ---------------- tiny kernels ----------------
__global__ void k_zero() {
    int i = blockIdx.x * blockDim.x + threadIdx.x;
    if (i < N_NODES) g_agg[i] = 0.0f;
}

__global__ void k_scatter(const float* __restrict__ x, const int* __restrict__ ei) {
    int i = blockIdx.x * blockDim.x + threadIdx.x;
    if (i < N_EDGES / 4) {
        const int4 s = reinterpret_cast<const int4*>(ei)[i];
        const int4 d = reinterpret_cast<const int4*>(ei + N_EDGES)[i];
        atomicAdd(&g_agg[d.x], x[s.x]);
        atomicAdd(&g_agg[d.y], x[s.y]);
        atomicAdd(&g_agg[d.z], x[s.z]);
        atomicAdd(&g_agg[d.w], x[s.w]);
    }
}

__device__ __forceinline__ uint32_t packh2(float v0, float v1) {
    __half2 h = __floats2half2_rn(v0, v1);
    return *reinterpret_cast<uint32_t*>(&h);
}

// Pack w_hid into per-lane mma B-fragment order (single fp16):
// idx = ((l*13+kc)*25+nt)*32 + lane -> uint2 {b0, b1}
__global__ void k_prep(const float* __restrict__ w_hid) {
    int idx = blockIdx.x * blockDim.x + threadIdx.x;
    if (idx >= NHID * NKC * NNT * 32) return;
    int lane = idx & 31;
    int u = idx >> 5;
    int nt = u % NNT; u /= NNT;
    int kc = u % NKC; int l = u / NKC;
    int t = lane & 3, g = lane >> 2;
    int n = nt * 8 + g;
    int k0 = kc * 16 + t * 2;
    float w00 = (k0     < HIDDEN) ? w_hid[((size_t)l * HIDDEN + k0    ) * HIDDEN + n] : 0.f;
    float w01 = (k0 + 1 < HIDDEN) ? w_hid[((size_t)l * HIDDEN + k0 + 1) * HIDDEN + n] : 0.f;
    float w10 = (k0 + 8 < HIDDEN) ? w_hid[((size_t)l * HIDDEN + k0 + 8) * HIDDEN + n] : 0.f;
    float w11 = (k0 + 9 < HIDDEN) ? w_hid[((size_t)l * HIDDEN + k0 + 9) * HIDDEN + n] : 0.f;
    uint2 v;
    v.x = packh2(w00, w01);
    v.y = packh2(w10, w11);
    g_wimg[idx] = v;
}

// ---------------- asm helpers ----------------
__device__ __forceinline__ uint32_t s2u(const void* p) {
    uint32_t a;
    asm("{ .reg .u64 t; cvta.to.shared.u64 t, %1; cvt.u32.u64 %0, t; }" : "=r"(a) : "l"(p));
    return a;
}
__device__ __forceinline__ void cp16(uint32_t sdst, const void* gsrc) {
    asm volatile("cp.async.cg.shared.global [%0], [%1], 16;" :: "r"(sdst), "l"(gsrc));
}
#define CP_COMMIT() asm volatile("cp.async.commit_group;")
#define CP_WAIT2()  asm volatile("cp.async.wait_group 2;")

__device__ __forceinline__ void ldsm4(uint32_t* r, uint32_t a) {
    asm volatile("ldmatrix.sync.aligned.m8n8.x4.shared.b16 {%0,%1,%2,%3}, [%4];"
        : "=r"(r[0]), "=r"(r[1]), "=r"(r[2]), "=r"(r[3]) : "r"(a));
}
__device__ __forceinline__ uint2 lds64(uint32_t a) {
    uint2 v;
    asm volatile("ld.shared.v2.u32 {%0,%1}, [%2];" : "=r"(v.x), "=r"(v.y) : "r"(a));
    return v;
}
__device__ __forceinline__ void sts32(uint32_t a, uint32_t v) {
    asm volatile("st.shared.u32 [%0], %1;" :: "r"(a), "r"(v));
}
__device__ __forceinline__ void mma16816(float* d, const uint32_t* a, uint32_t b0, uint32_t b1) {
    asm volatile("mma.sync.aligned.m16n8k16.row.col.f32.f16.f16.f32 "
        "{%0,%1,%2,%3}, {%4,%5,%6,%7}, {%8,%9}, {%0,%1,%2,%3};"
        : "+f"(d[0]), "+f"(d[1]), "+f"(d[2]), "+f"(d[3])
        : "r"(a[0]), "r"(a[1]), "r"(a[2]), "r"(a[3]), "r"(b0), "r"(b1));
}

// ---------------- templated layer MMA loop ----------------
template<int NTB, int NNTW>
__device__ __forceinline__ void layer_mmas(
    float (*d)[4], int l, int tid, int lane, uint32_t sb, uint32_t aAddr)
{
    for (int kc = 0; kc < NKC; ++kc) {
        const int st = l * NKC + kc;
        CP_WAIT2();
        __syncthreads();

        uint32_t a[4];
        ldsm4(a, aAddr + kc * 32);

        // issue next prefetch FIRST so cp.async overlaps the MMA burst
        if (st + 3 < NSTAGE) {
            const char* src = reinterpret_cast<const char*>(g_wimg) + (size_t)(st + 3) * SLAB_B;
            uint32_t dst = sb + RING_OFF + ((st + 3) & 3) * SLAB_B;
            #pragma unroll
            for (int c = 0; c < (SLAB_B / 16 + THREADS - 1) / THREADS; ++c) {
                int idx = tid + c * THREADS;
                if (idx < SLAB_B / 16) cp16(dst + idx * 16, src + idx * 16);
            }
        }
        CP_COMMIT();

        const uint32_t bbase = sb + RING_OFF + (st & 3) * SLAB_B + lane * 8 + NTB * 256;
        #pragma unroll
        for (int nt = 0; nt < NNTW; ++nt) {
            uint2 B = lds64(bbase + nt * 256);
            mma16816(d[nt], a, B.x, B.y);
        }
    }
    __syncthreads();   // all ldsm reads of this layer's A done before epilogue overwrites A
}

template<int NTB, int NNTW>
__device__ __forceinline__ void epi_store(
    const float (*d)[4], const float* biasL, int wm, int g, int t, uint32_t sb)
{
    const uint32_t off0 = (uint32_t)(wm * 16 + g) * ASTRIDE;
    #pragma unroll
    for (int nt = 0; nt < NNTW; ++nt) {
        int c0 = 8 * (NTB + nt) + 2 * t;
        float b0 = biasL[c0], b1 = biasL[c0 + 1];
        float v0 = fmaxf(d[nt][0] + b0, 0.f), v1 = fmaxf(d[nt][1] + b1, 0.f);
        float v2 = fmaxf(d[nt][2] + b0, 0.f), v3 = fmaxf(d[nt][3] + b1, 0.f);
        uint32_t a0 = off0 + (uint32_t)c0 * 2;
        uint32_t a1 = a0 + 8 * ASTRIDE;
        sts32(sb + A_OFF + a0, packh2(v0, v1));
        sts32(sb + A_OFF + a1, packh2(v2, v3));
    }
}

template<int NTB, int NNTW>
__device__ __forceinline__ void epi_final(
    const float (*d)[4], const float* biasL, const float* woutS,
    float* zp, int h, int wm, int g, int t)
{
    float z0 = 0.f, z1 = 0.f;
    #pragma unroll
    for (int nt = 0; nt < NNTW; ++nt) {
        int c0 = 8 * (NTB + nt) + 2 * t;
        float b0 = biasL[c0], b1 = biasL[c0 + 1];
        float w0 = woutS[c0], w1 = woutS[c0 + 1];
        z0 = fmaf(fmaxf(d[nt][0] + b0, 0.f), w0, z0);
        z0 = fmaf(fmaxf(d[nt][1] + b1, 0.f), w1, z0);
        z1 = fmaf(fmaxf(d[nt][2] + b0, 0.f), w0, z1);
        z1 = fmaf(fmaxf(d[nt][3] + b1, 0.f), w1, z1);
    }
    z0 += __shfl_xor_sync(0xffffffffu, z0, 1);
    z0 += __shfl_xor_sync(0xffffffffu, z0, 2);
    z1 += __shfl_xor_sync(0xffffffffu, z1, 1);
    z1 += __shfl_xor_sync(0xffffffffu, z1, 2);
    if (t == 0) {
        int rl = wm * 16 + g;
        zp[h * TM + rl]     = z0;
        zp[h * TM + rl + 8] = z1;
    }
}

// ---------------- fused GraphConv + MLP + sigmoid ----------------
__global__ void __launch_bounds__(THREADS, 3) k_mlp(
    const float* __restrict__ x,
    const float* __restrict__ w_rel, const float* __restrict__ b_rel,
    const float* __restrict__ w_root,
    const float* __restrict__ w_in,  const float* __restrict__ b_in,
    const float* __restrict__ b_hid,
    const float* __restrict__ w_out, const float* __restrict__ b_out,
    float* __restrict__ out)
{
    extern __shared__ char smem[];
    const uint32_t sb = s2u(smem);
    const int tid  = threadIdx.x;
    const int warp = tid >> 5;
    const int lane = tid & 31;
    const int h    = warp >> 2;        // n-half: 0 -> tiles 0..12, 1 -> tiles 13..24
    const int wm   = warp & 3;         // row block: rows wm*16..wm*16+15
    const int g    = lane >> 2;
    const int t    = lane & 3;
    const int row0 = blockIdx.x * TM;

    float* biasS = reinterpret_cast<float*>(smem + BIAS_OFF);   // [6][200]
    float* woutS = reinterpret_cast<float*>(smem + WOUT_OFF);
    float* h0S   = reinterpret_cast<float*>(smem + H0_OFF);
    float* zp    = reinterpret_cast<float*>(smem + ZP_OFF);

    // stage small vectors + h0
    if (tid < HIDDEN) woutS[tid] = __ldg(w_out + tid);
    for (int i = tid; i < NHID * HIDDEN; i += THREADS) biasS[i] = __ldg(b_hid + i);
    if (tid < TM) {
        int r = row0 + tid;
        float a  = (r < N_NODES) ? g_agg[r] : 0.0f;
        float xv = (r < N_NODES) ? __ldg(x + r) : 0.0f;
        h0S[tid] = a * __ldg(w_rel) + __ldg(b_rel) + xv * __ldg(w_root);
    }
    __syncthreads();

    // layer-1 activations (rank-1): A[r][k] = relu(h0[r]*w_in[k]+b_in[k]), k>=200 -> 0
    for (int i = tid; i < TM * 208; i += THREADS) {
        int r = i / 208, k = i - r * 208;
        float v = 0.0f;
        if (k < HIDDEN) v = fmaxf(fmaf(h0S[r], __ldg(w_in + k), __ldg(b_in + k)), 0.0f);
        *reinterpret_cast<__half*>(smem + A_OFF + r * ASTRIDE + k * 2) = __float2half_rn(v);
    }

    // prefetch weight slabs 0..2
    #pragma unroll
    for (int ps = 0; ps < 3; ++ps) {
        const char* src = reinterpret_cast<const char*>(g_wimg) + (size_t)ps * SLAB_B;
        uint32_t dst = sb + RING_OFF + ps * SLAB_B;
        for (int c = tid; c < SLAB_B / 16; c += THREADS)
            cp16(dst + c * 16, src + c * 16);
        CP_COMMIT();
    }

    // ldmatrix per-lane address (rows wm*16 .. +15)
    const int lrow = lane & 15;
    const uint32_t aAddr = sb + A_OFF + (wm * 16 + lrow) * ASTRIDE + (lane >> 4) * 16;

    float d[13][4];

    for (int l = 0; l < NHID; ++l) {
        #pragma unroll
        for (int nt = 0; nt < 13; ++nt) {
            d[nt][0] = 0.f; d[nt][1] = 0.f; d[nt][2] = 0.f; d[nt][3] = 0.f;
        }

        if (h == 0) layer_mmas<0, 13>(d, l, tid, lane, sb, aAddr);
        else        layer_mmas<13, 12>(d, l, tid, lane, sb, aAddr);

        const float* biasL = biasS + l * HIDDEN;
        if (l < NHID - 1) {
            if (h == 0) epi_store<0, 13>(d, biasL, wm, g, t, sb);
            else        epi_store<13, 12>(d, biasL, wm, g, t, sb);
        } else {
            if (h == 0) epi_final<0, 13>(d, biasL, woutS, zp, h, wm, g, t);
            else        epi_final<13, 12>(d, biasL, woutS, zp, h, wm, g, t);
        }
    }

    __syncthreads();
    if (tid < TM) {
        int r = row0 + tid;
        if (r < N_NODES) {
            float z = zp[tid] + zp[TM + tid] + __ldg(b_out);
            out[r] = 1.0f / (1.0f + expf(-z));
        }
    }
}

// ---------------- launch ----------------
extern "C" void kernel_launch(void* const* d_in, const int* in_sizes, int n_in,
                              void* d_out, int out_size)
{
    const float* x      = (const float*)d_in[0];
    const int*   ei     = (const int*)d_in[1];      // int32 (jax x64 disabled)
    const float* w_rel  = (const float*)d_in[2];
    const float* b_rel  = (const float*)d_in[3];
    const float* w_root = (const float*)d_in[4];
    const float* w_in   = (const float*)d_in[5];
    const float* b_in   = (const float*)d_in[6];
    const float* w_hid  = (const float*)d_in[7];
    const float* b_hid  = (const float*)d_in[8];
    const float* w_out  = (const float*)d_in[9];
    const float* b_out  = (const float*)d_in[10];
    float*       out    = (float*)d_out;

    cudaFuncSetAttribute(k_mlp, cudaFuncAttributeMaxDynamicSharedMemorySize, SMEM_BYTES);

    k_prep<<<(NHID * NKC * NNT * 32 + 255) / 256, 256>>>(w_hid);
    k_zero<<<(N_NODES + 255) / 256, 256>>>();
    k_scatter<<<(N_EDGES / 4 + 255) / 256, 256>>>(x, ei);
    k_mlp<<<NCTA, THREADS, SMEM_BYTES>>>(
        x, w_rel, b_rel, w_root, w_in, b_in, b_hid, w_out, b_out, out);
}